// round 4
// baseline (speedup 1.0000x reference)
#include <cuda_runtime.h>
#include <cuda_fp16.h>
#include <cstdint>

// out[b,n,f] = sum_m A[b,n,m] * X[b,m,f] + bias[f]
// A: [8,4096,4096] fp32, X: [8,4096,64] fp32, bias [64].
//
// fp16 mma.sync GEMM, persistent exact-fit grid:
//  - grid = 8 batches x 37 CTAs = 296 = 2 x 148 SMs (one full wave, occ 2).
//    CTA j of a batch owns M row-groups [floor(j*256/37), floor((j+1)*256/37))
//    (6 or 7 groups of 16 rows) -> 1.2% quantization instead of 15%.
//  - A loaded raw fp32 via cp.async.cg, 4-stage pipeline (3 chunks in flight),
//    converted fp32->fp16 in a warp-local smem pass (LDS.128 -> cvt -> STS.64,
//    double-buffered per-warp fp16 tile). B (g_Xt, fp16) cp.async'd directly.
//  - compute: ldmatrix + mma.sync.m16n8k16, fp32 accum; epilogue adds bias.

#define NBATCH   8
#define NN       4096
#define FF       64
#define KC       32
#define NCH      (NN / KC)     // 128
#define STAGES   4
#define CTAS_B   37            // CTAs per batch; grid = 296 = 2*148
#define MAXG     7             // max row-groups per CTA

#define A32_ST   (MAXG * 16 * 128)   // 14336 B: 112 rows x 32 fp32
#define B16_ST   (FF * 64)           // 4096 B:  64 rows x 32 fp16
#define A16_ST   (MAXG * 16 * 64)    // 7168 B:  112 rows x 32 fp16
#define OFF_A32  0
#define OFF_B16  (STAGES * A32_ST)                 // 57344
#define OFF_A16  (OFF_B16 + STAGES * B16_ST)       // 73728
#define SMEM_USE (OFF_A16 + 2 * A16_ST)            // 88064
#define SMEM_DYN (SMEM_USE + 1024)

__device__ __half g_Xt[NBATCH * FF * NN];   // [b][f][k] fp16

__device__ __forceinline__ uint32_t smem_u32(const void* p) {
    uint32_t a;
    asm("{ .reg .u64 t; cvta.to.shared.u64 t, %1; cvt.u32.u64 %0, t; }"
        : "=r"(a) : "l"(p));
    return a;
}
#define SW128(o) ((o) ^ (((o) >> 3) & 0x70))
#define SW64(o)  ((o) ^ (((o) >> 3) & 0x30))

#define CP16(dst, src) \
    asm volatile("cp.async.cg.shared.global [%0], [%1], 16;" \
                 :: "r"(dst), "l"(src) : "memory")
#define CP_COMMIT() asm volatile("cp.async.commit_group;" ::: "memory")
#define CP_WAIT3()  asm volatile("cp.async.wait_group 3;" ::: "memory")

// ---------- prep: Xt[b][f][k] = fp16(X[b][k][f]) ----------
__global__ __launch_bounds__(256) void prep_xt_kernel(const float* __restrict__ X) {
    __shared__ float t[32][FF + 1];
    const int b  = blockIdx.y;
    const int k0 = blockIdx.x * 32;
    const int tx = threadIdx.x;   // 0..31
    const int ty = threadIdx.y;   // 0..7
#pragma unroll
    for (int i = 0; i < 4; ++i) {
        const int r = ty + 8 * i;
        const float* src = X + ((size_t)b * NN + k0 + r) * FF;
        t[r][tx]      = src[tx];
        t[r][tx + 32] = src[tx + 32];
    }
    __syncthreads();
#pragma unroll
    for (int j = 0; j < 8; ++j) {
        const int f = ty + 8 * j;
        g_Xt[((size_t)b * FF + f) * NN + k0 + tx] = __float2half_rn(t[tx][f]);
    }
}

// ---------- main GEMM ----------
__global__ __launch_bounds__(256, 2) void gemm_f16_persist(
    const float* __restrict__ A,
    const float* __restrict__ bias,
    float* __restrict__ out)
{
    extern __shared__ char ds[];
    const uint32_t sb = (smem_u32(ds) + 1023u) & ~1023u;

    const int tid  = threadIdx.x;
    const int wid  = tid >> 5;
    const int lane = tid & 31;

    const int b  = blockIdx.x / CTAS_B;
    const int ct = blockIdx.x % CTAS_B;
    const int g0 = (ct * 256) / CTAS_B;
    const int g1 = ((ct + 1) * 256) / CTAS_B;
    const int NG = g1 - g0;            // 6 or 7
    const int nrows = NG * 16;
    const int asegs = nrows * 8;       // 16B fp32 segments per A chunk

    const float*  Ab = A + ((size_t)b * NN + (size_t)g0 * 16) * NN;
    const __half* Xb = g_Xt + (size_t)b * FF * NN;

    // B cp.async addressing: one 16B seg per thread per chunk
    const int bn = tid >> 2;           // 0..63
    const int bs = tid & 3;            // 0..3 (k 16B-seg)
    const uint32_t b_dst_off = SW64((uint32_t)(bn * 64 + bs * 16));
    const __half* b_src_row = Xb + (size_t)bn * NN + bs * 8;

    // ldmatrix lane decomposition
    const int li = lane >> 3;          // matrix id 0..3
    const int lr = lane & 7;           // row within matrix
    const uint32_t a_off =
        (uint32_t)((wid * 16 + (li & 1) * 8 + lr) * 64 + (li >> 1) * 16);
    const uint32_t b_off =
        (uint32_t)(((li >> 1) * 8 + lr) * 64 + (li & 1) * 16);

    // convert-pass addressing (warp-local rows 16*wid .. +15)
    const int cv_row = wid * 16 + (lane >> 3);  // + 4*i
    const int cv_s   = lane & 7;

    float acc[8][4];
#pragma unroll
    for (int n = 0; n < 8; ++n)
#pragma unroll
        for (int j = 0; j < 4; ++j) acc[n][j] = 0.0f;

    // ---- prologue: issue chunks 0..2 ----
#pragma unroll
    for (int c0 = 0; c0 < STAGES - 1; ++c0) {
        const uint32_t a_dst = sb + OFF_A32 + (uint32_t)c0 * A32_ST;
        const uint32_t b_dst = sb + OFF_B16 + (uint32_t)c0 * B16_ST;
        const float* a_src = Ab + (size_t)c0 * KC;
        for (int seg = tid; seg < asegs; seg += 256) {
            const int row = seg >> 3, s = seg & 7;
            CP16(a_dst + SW128((uint32_t)(row * 128 + s * 16)),
                 a_src + (size_t)row * NN + s * 4);
        }
        CP16(b_dst + b_dst_off, b_src_row + (size_t)c0 * KC);
        CP_COMMIT();
    }

    int cb = 0;
    for (int c = 0; c < NCH; ++c) {
        // WAR guard: everyone finished compute(c-1) before stage (c-1)%4 refill
        __syncthreads();

        if (c + STAGES - 1 < NCH) {
            const int cn = c + STAGES - 1;
            const int st = cn & (STAGES - 1);
            const uint32_t a_dst = sb + OFF_A32 + (uint32_t)st * A32_ST;
            const uint32_t b_dst = sb + OFF_B16 + (uint32_t)st * B16_ST;
            const float* a_src = Ab + (size_t)cn * KC;
            for (int seg = tid; seg < asegs; seg += 256) {
                const int row = seg >> 3, s = seg & 7;
                CP16(a_dst + SW128((uint32_t)(row * 128 + s * 16)),
                     a_src + (size_t)row * NN + s * 4);
            }
            CP16(b_dst + b_dst_off, b_src_row + (size_t)cn * KC);
        }
        CP_COMMIT();                 // unconditional: keeps group counting uniform
        CP_WAIT3();                  // chunk c's group complete
        __syncthreads();             // make it visible to all threads

        if (wid < NG) {
            const uint32_t a32 = sb + OFF_A32 + (uint32_t)(c & (STAGES - 1)) * A32_ST;
            const uint32_t b16 = sb + OFF_B16 + (uint32_t)(c & (STAGES - 1)) * B16_ST;
            const uint32_t a16 = sb + OFF_A16 + (uint32_t)cb * A16_ST;

            // -- convert this warp's 16 rows: fp32 smem -> fp16 smem --
#pragma unroll
            for (int i = 0; i < 4; ++i) {
                const int row = cv_row + 4 * i;
                uint32_t r0, r1, r2, r3;
                asm volatile("ld.shared.v4.b32 {%0,%1,%2,%3}, [%4];"
                             : "=r"(r0), "=r"(r1), "=r"(r2), "=r"(r3)
                             : "r"(a32 + SW128((uint32_t)(row * 128 + cv_s * 16))));
                __half2 h0 = __floats2half2_rn(__uint_as_float(r0), __uint_as_float(r1));
                __half2 h1 = __floats2half2_rn(__uint_as_float(r2), __uint_as_float(r3));
                asm volatile("st.shared.v2.b32 [%0], {%1, %2};"
                             :: "r"(a16 + SW64((uint32_t)(row * 64 + cv_s * 8))),
                                "r"(*(uint32_t*)&h0), "r"(*(uint32_t*)&h1)
                             : "memory");
            }
            __syncwarp();

            // -- compute: 2 k16-steps --
#pragma unroll
            for (int ks = 0; ks < 2; ++ks) {
                uint32_t a0, a1, a2, a3;
                asm volatile(
                    "ldmatrix.sync.aligned.m8n8.x4.shared.b16 {%0,%1,%2,%3}, [%4];"
                    : "=r"(a0), "=r"(a1), "=r"(a2), "=r"(a3)
                    : "r"(a16 + SW64(a_off + (uint32_t)ks * 32)));
#pragma unroll
                for (int p = 0; p < 4; ++p) {
                    uint32_t b0, b1, b2, b3;
                    asm volatile(
                        "ldmatrix.sync.aligned.m8n8.x4.shared.b16 {%0,%1,%2,%3}, [%4];"
                        : "=r"(b0), "=r"(b1), "=r"(b2), "=r"(b3)
                        : "r"(b16 + SW64(b_off + (uint32_t)p * 1024 + (uint32_t)ks * 32)));
                    asm volatile(
                        "mma.sync.aligned.m16n8k16.row.col.f32.f16.f16.f32 "
                        "{%0,%1,%2,%3}, {%4,%5,%6,%7}, {%8,%9}, {%0,%1,%2,%3};"
                        : "+f"(acc[2*p][0]), "+f"(acc[2*p][1]),
                          "+f"(acc[2*p][2]), "+f"(acc[2*p][3])
                        : "r"(a0), "r"(a1), "r"(a2), "r"(a3), "r"(b0), "r"(b1));
                    asm volatile(
                        "mma.sync.aligned.m16n8k16.row.col.f32.f16.f16.f32 "
                        "{%0,%1,%2,%3}, {%4,%5,%6,%7}, {%8,%9}, {%0,%1,%2,%3};"
                        : "+f"(acc[2*p+1][0]), "+f"(acc[2*p+1][1]),
                          "+f"(acc[2*p+1][2]), "+f"(acc[2*p+1][3])
                        : "r"(a0), "r"(a1), "r"(a2), "r"(a3), "r"(b2), "r"(b3));
                }
            }
        }
        cb ^= 1;
    }

    // ---- epilogue: add bias, store ----
    if (wid < NG) {
        const int g = lane >> 2, q = lane & 3;
        const int mlo = (g0 + wid) * 16 + g;
        float* o0 = out + ((size_t)b * NN + mlo) * FF;
        float* o1 = o0 + (size_t)8 * FF;
#pragma unroll
        for (int nt = 0; nt < 8; ++nt) {
            const int col = nt * 8 + q * 2;
            const float2 bv = *reinterpret_cast<const float2*>(bias + col);
            float2 v0 = make_float2(acc[nt][0] + bv.x, acc[nt][1] + bv.y);
            float2 v1 = make_float2(acc[nt][2] + bv.x, acc[nt][3] + bv.y);
            *reinterpret_cast<float2*>(o0 + col) = v0;
            *reinterpret_cast<float2*>(o1 + col) = v1;
        }
    }
}

extern "C" void kernel_launch(void* const* d_in, const int* in_sizes, int n_in,
                              void* d_out, int out_size)
{
    const float* A    = (const float*)d_in[0]; // adjacent [8,4096,4096]
    const float* X    = (const float*)d_in[1]; // annotations [8,4096,64]
    const float* bias = (const float*)d_in[2]; // bias [1,1,64]
    float* out = (float*)d_out;

    cudaFuncSetAttribute(gemm_f16_persist,
                         cudaFuncAttributeMaxDynamicSharedMemorySize, SMEM_DYN);

    dim3 pg(NN / 32, NBATCH);
    dim3 pbk(32, 8);
    prep_xt_kernel<<<pg, pbk>>>(X);

    gemm_f16_persist<<<NBATCH * CTAS_B, 256, SMEM_DYN>>>(A, bias, out);
}

// round 5
// speedup vs baseline: 1.0806x; 1.0806x over previous
#include <cuda_runtime.h>
#include <cuda_fp16.h>
#include <cstdint>

// out[b,n,f] = sum_m A[b,n,m] * X[b,m,f] + bias[f]
// A: [8,4096,4096] fp32, X: [8,4096,64] fp32, bias [64].
//
// R3 kernel (fp16 mma.sync, register-staged double-buffer, KC=64) with ONLY
// the grid changed: 8 x 37 = 296 CTAs = exactly 2 per SM (one full wave).
// CTA j of a batch owns row-groups [floor(j*256/37), floor((j+1)*256/37))
// -> 6 or 7 groups of 16 rows. All 8 warps load; warps 0..NG-1 compute.

#define NBATCH  8
#define NN      4096
#define FF      64
#define KC      64
#define NCH     (NN / KC)       // 64
#define CTAS_B  37              // grid = 296 = 2*148
#define MAXG    7

#define AST     (MAXG * 16 * 128)   // 14336 B: 112 rows x 64 fp16
#define BST     (FF * 128)          // 8192 B:  64 rows x 64 fp16
#define STB     (AST + BST)         // 22528
#define SMEM_DYN (2 * STB)          // 45056

__device__ __half g_Xt[NBATCH * FF * NN];   // [b][f][k] fp16

__device__ __forceinline__ uint32_t smem_u32(const void* p) {
    uint32_t a;
    asm("{ .reg .u64 t; cvta.to.shared.u64 t, %1; cvt.u32.u64 %0, t; }"
        : "=r"(a) : "l"(p));
    return a;
}
#define SW(o) ((o) ^ (((o) >> 3) & 0x70))

// ---------- prep: Xt[b][f][k] = fp16(X[b][k][f]) ----------
__global__ __launch_bounds__(256) void prep_xt_kernel(const float* __restrict__ X) {
    __shared__ float t[32][FF + 1];
    const int b  = blockIdx.y;
    const int k0 = blockIdx.x * 32;
    const int tx = threadIdx.x;   // 0..31
    const int ty = threadIdx.y;   // 0..7
#pragma unroll
    for (int i = 0; i < 4; ++i) {
        const int r = ty + 8 * i;
        const float* src = X + ((size_t)b * NN + k0 + r) * FF;
        t[r][tx]      = src[tx];
        t[r][tx + 32] = src[tx + 32];
    }
    __syncthreads();
#pragma unroll
    for (int j = 0; j < 8; ++j) {
        const int f = ty + 8 * j;
        g_Xt[((size_t)b * FF + f) * NN + k0 + tx] = __float2half_rn(t[tx][f]);
    }
}

// ---------- main GEMM ----------
__global__ __launch_bounds__(256, 2) void gemm_f16_persist(
    const float* __restrict__ A,
    const float* __restrict__ bias,
    float* __restrict__ out)
{
    extern __shared__ char ds[];
    const uint32_t sb = smem_u32(ds);

    const int tid  = threadIdx.x;
    const int wid  = tid >> 5;
    const int lane = tid & 31;

    const int b  = blockIdx.x / CTAS_B;
    const int ct = blockIdx.x % CTAS_B;
    const int g0 = (ct * 256) / CTAS_B;
    const int g1 = ((ct + 1) * 256) / CTAS_B;
    const int NG = g1 - g0;             // 6 or 7
    const int nrows = NG * 16;

    const float*  Ab = A + ((size_t)b * NN + (size_t)g0 * 16) * NN;
    const __half* Xb = g_Xt + (size_t)b * FF * NN;

    // producer addressing (constant per thread)
    const int arow = tid >> 4;    // A: row base 0..15 (+16*i), 16 float4/row
    const int ac4  = tid & 15;    //    float4 index within row
    const int brow = tid >> 3;    // B: row base 0..31 (+32*i), 8 uint4/row
    const int bc   = tid & 7;     //    uint4 (16B) index within row

    // ldmatrix lane decomposition
    const int li = lane >> 3;     // matrix id 0..3
    const int lr = lane & 7;      // row within matrix
    const uint32_t a_off =
        (uint32_t)((wid * 16 + (li & 1) * 8 + lr) * 128 + (li >> 1) * 16);
    const uint32_t b_off =
        (uint32_t)(((li >> 1) * 8 + lr) * 128 + (li & 1) * 16);

    float acc[8][4];
#pragma unroll
    for (int n = 0; n < 8; ++n)
#pragma unroll
        for (int j = 0; j < 4; ++j) acc[n][j] = 0.0f;

    float4 pa[MAXG];
    uint4  pb[2];

    // ---- prologue: load + stage chunk 0 ----
#pragma unroll
    for (int i = 0; i < MAXG; ++i)
        if (16 * i < nrows)
            pa[i] = *reinterpret_cast<const float4*>(
                Ab + (size_t)(arow + 16 * i) * NN + ac4 * 4);
#pragma unroll
    for (int i = 0; i < 2; ++i)
        pb[i] = *reinterpret_cast<const uint4*>(
            Xb + (size_t)(brow + 32 * i) * NN + bc * 8);
    {
        const uint32_t as = sb, bs = sb + AST;
#pragma unroll
        for (int i = 0; i < MAXG; ++i)
            if (16 * i < nrows) {
                __half2 h0 = __floats2half2_rn(pa[i].x, pa[i].y);
                __half2 h1 = __floats2half2_rn(pa[i].z, pa[i].w);
                const uint32_t off =
                    as + SW((uint32_t)((arow + 16 * i) * 128 + ac4 * 8));
                asm volatile("st.shared.v2.b32 [%0], {%1, %2};" :: "r"(off),
                             "r"(*(uint32_t*)&h0), "r"(*(uint32_t*)&h1) : "memory");
            }
#pragma unroll
        for (int i = 0; i < 2; ++i) {
            const uint32_t off =
                bs + SW((uint32_t)((brow + 32 * i) * 128 + bc * 16));
            asm volatile("st.shared.v4.b32 [%0], {%1,%2,%3,%4};" :: "r"(off),
                         "r"(pb[i].x), "r"(pb[i].y), "r"(pb[i].z), "r"(pb[i].w)
                         : "memory");
        }
    }
    __syncthreads();

    for (int c = 0; c < NCH; ++c) {
        // prefetch next chunk into registers
        if (c + 1 < NCH) {
            const int kn = (c + 1) * KC;
#pragma unroll
            for (int i = 0; i < MAXG; ++i)
                if (16 * i < nrows)
                    pa[i] = *reinterpret_cast<const float4*>(
                        Ab + (size_t)(arow + 16 * i) * NN + kn + ac4 * 4);
#pragma unroll
            for (int i = 0; i < 2; ++i)
                pb[i] = *reinterpret_cast<const uint4*>(
                    Xb + (size_t)(brow + 32 * i) * NN + kn + bc * 8);
        }

        // compute chunk c from stage (c&1)
        if (wid < NG) {
            const uint32_t as = sb + (uint32_t)(c & 1) * STB;
            const uint32_t bs = as + AST;
#pragma unroll
            for (int ks = 0; ks < 4; ++ks) {
                uint32_t a0, a1, a2, a3;
                asm volatile(
                    "ldmatrix.sync.aligned.m8n8.x4.shared.b16 {%0,%1,%2,%3}, [%4];"
                    : "=r"(a0), "=r"(a1), "=r"(a2), "=r"(a3)
                    : "r"(as + SW(a_off + (uint32_t)ks * 32)));
#pragma unroll
                for (int p = 0; p < 4; ++p) {
                    uint32_t b0, b1, b2, b3;
                    asm volatile(
                        "ldmatrix.sync.aligned.m8n8.x4.shared.b16 {%0,%1,%2,%3}, [%4];"
                        : "=r"(b0), "=r"(b1), "=r"(b2), "=r"(b3)
                        : "r"(bs + SW(b_off + (uint32_t)p * 2048 + (uint32_t)ks * 32)));
                    asm volatile(
                        "mma.sync.aligned.m16n8k16.row.col.f32.f16.f16.f32 "
                        "{%0,%1,%2,%3}, {%4,%5,%6,%7}, {%8,%9}, {%0,%1,%2,%3};"
                        : "+f"(acc[2*p][0]), "+f"(acc[2*p][1]),
                          "+f"(acc[2*p][2]), "+f"(acc[2*p][3])
                        : "r"(a0), "r"(a1), "r"(a2), "r"(a3), "r"(b0), "r"(b1));
                    asm volatile(
                        "mma.sync.aligned.m16n8k16.row.col.f32.f16.f16.f32 "
                        "{%0,%1,%2,%3}, {%4,%5,%6,%7}, {%8,%9}, {%0,%1,%2,%3};"
                        : "+f"(acc[2*p+1][0]), "+f"(acc[2*p+1][1]),
                          "+f"(acc[2*p+1][2]), "+f"(acc[2*p+1][3])
                        : "r"(a0), "r"(a1), "r"(a2), "r"(a3), "r"(b2), "r"(b3));
                }
            }
        }

        // stage chunk c+1 into the other buffer
        if (c + 1 < NCH) {
            const uint32_t as2 = sb + (uint32_t)((c + 1) & 1) * STB;
            const uint32_t bs2 = as2 + AST;
#pragma unroll
            for (int i = 0; i < MAXG; ++i)
                if (16 * i < nrows) {
                    __half2 h0 = __floats2half2_rn(pa[i].x, pa[i].y);
                    __half2 h1 = __floats2half2_rn(pa[i].z, pa[i].w);
                    const uint32_t off =
                        as2 + SW((uint32_t)((arow + 16 * i) * 128 + ac4 * 8));
                    asm volatile("st.shared.v2.b32 [%0], {%1, %2};" :: "r"(off),
                                 "r"(*(uint32_t*)&h0), "r"(*(uint32_t*)&h1)
                                 : "memory");
                }
#pragma unroll
            for (int i = 0; i < 2; ++i) {
                const uint32_t off =
                    bs2 + SW((uint32_t)((brow + 32 * i) * 128 + bc * 16));
                asm volatile("st.shared.v4.b32 [%0], {%1,%2,%3,%4};" :: "r"(off),
                             "r"(pb[i].x), "r"(pb[i].y), "r"(pb[i].z), "r"(pb[i].w)
                             : "memory");
            }
        }
        __syncthreads();
    }

    // ---- epilogue: add bias, store ----
    if (wid < NG) {
        const int g = lane >> 2, q = lane & 3;
        const int mlo = (g0 + wid) * 16 + g;
        float* o0 = out + ((size_t)b * NN + mlo) * FF;
        float* o1 = o0 + (size_t)8 * FF;
#pragma unroll
        for (int nt = 0; nt < 8; ++nt) {
            const int col = nt * 8 + q * 2;
            const float2 bv = *reinterpret_cast<const float2*>(bias + col);
            float2 v0 = make_float2(acc[nt][0] + bv.x, acc[nt][1] + bv.y);
            float2 v1 = make_float2(acc[nt][2] + bv.x, acc[nt][3] + bv.y);
            *reinterpret_cast<float2*>(o0 + col) = v0;
            *reinterpret_cast<float2*>(o1 + col) = v1;
        }
    }
}

extern "C" void kernel_launch(void* const* d_in, const int* in_sizes, int n_in,
                              void* d_out, int out_size)
{
    const float* A    = (const float*)d_in[0]; // adjacent [8,4096,4096]
    const float* X    = (const float*)d_in[1]; // annotations [8,4096,64]
    const float* bias = (const float*)d_in[2]; // bias [1,1,64]
    float* out = (float*)d_out;

    cudaFuncSetAttribute(gemm_f16_persist,
                         cudaFuncAttributeMaxDynamicSharedMemorySize, SMEM_DYN);

    dim3 pg(NN / 32, NBATCH);
    dim3 pbk(32, 8);
    prep_xt_kernel<<<pg, pbk>>>(X);

    gemm_f16_persist<<<NBATCH * CTAS_B, 256, SMEM_DYN>>>(A, bias, out);
}